// round 1
// baseline (speedup 1.0000x reference)
#include <cuda_runtime.h>
#include <cstdint>

// Problem constants (fixed by the dataset)
#define BATCH   16
#define C_IN    64
#define HH      32
#define WW      32
#define C_OUT   128
#define NGATE   4          // only weight rows 0..3 are ever used by the tree
#define PH      34         // padded plane height
#define PW      34         // padded plane width
#define PLANE   (PH*PW)    // 1156

// Scratch: per-(oc,gate) affine coefficients {c0, ca, cb, cab}
__device__ float g_coef[C_OUT * NGATE * 4];

// ---------------------------------------------------------------------------
// Kernel 1: softmax over the 16 ops, collapsed to 4 affine coefficients.
// Each of the 16 binary ops equals c0 + ca*a + cb*b + cab*a*b.
// ---------------------------------------------------------------------------
__global__ void coef_kernel(const float* __restrict__ w)
{
    // op order: 0, ab, a-ab, a, b-ab, b, s-2ab, s-ab, 1-(s-ab), 1-(s-2ab),
    //           1-b, 1-b+ab, 1-a, 1-a+ab, 1-ab, 1
    const float T0[16]  = {0,0,0,0,0,0,0,0, 1, 1, 1, 1, 1, 1, 1, 1};
    const float TA[16]  = {0,0,1,1,0,0,1,1,-1,-1, 0, 0,-1,-1, 0, 0};
    const float TB[16]  = {0,0,0,0,1,1,1,1,-1,-1,-1,-1, 0, 0, 0, 0};
    const float TAB[16] = {0,1,-1,0,-1,0,-2,-1, 1, 2, 0, 1, 0, 1,-1, 0};

    int t = blockIdx.x * blockDim.x + threadIdx.x;
    if (t >= C_OUT * NGATE) return;
    int oc = t >> 2;
    int g  = t & 3;
    const float* wp = w + (oc * 7 + g) * 16;   // weights are [C_out, 7, 16]

    float m = wp[0];
    #pragma unroll
    for (int i = 1; i < 16; i++) m = fmaxf(m, wp[i]);

    float e[16];
    float s = 0.f;
    #pragma unroll
    for (int i = 0; i < 16; i++) { e[i] = __expf(wp[i] - m); s += e[i]; }
    float inv = 1.f / s;

    float c0 = 0.f, ca = 0.f, cb = 0.f, cab = 0.f;
    #pragma unroll
    for (int i = 0; i < 16; i++) {
        c0  += e[i] * T0[i];
        ca  += e[i] * TA[i];
        cb  += e[i] * TB[i];
        cab += e[i] * TAB[i];
    }
    float* o = g_coef + t * 4;
    o[0] = c0 * inv; o[1] = ca * inv; o[2] = cb * inv; o[3] = cab * inv;
}

// gate(a,b) = c0 + ca*a + cb*b + cab*a*b
__device__ __forceinline__ float gate(float c0, float ca, float cb, float cab,
                                      float a, float b)
{
    return fmaf(cab, a * b, fmaf(cb, b, fmaf(ca, a, c0)));
}

// ---------------------------------------------------------------------------
// Kernel 2: one block per (batch, out_channel).
// Stage the 2 source channel planes (zero-padded 34x34) in smem, then each
// thread evaluates 4 output pixels through the 7-gate soft logic tree.
// ---------------------------------------------------------------------------
__global__ void __launch_bounds__(256)
tree_kernel(const float* __restrict__ x,
            const int*   __restrict__ leaf_idx,
            float*       __restrict__ out)
{
    __shared__ float sm[2 * PLANE];   // two padded planes
    __shared__ int   s_off[8];        // per-leaf: plane_base + ki*PW + kj
    __shared__ int   s_chan[2];       // the two source channels
    __shared__ float s_coef[16];      // 4 gates x {c0,ca,cb,cab}

    const int blk = blockIdx.x;       // = b*C_OUT + oc
    const int oc  = blk & (C_OUT - 1);
    const int b   = blk >> 7;
    const int tid = threadIdx.x;

    if (tid < 8) {
        int idx = leaf_idx[oc * 8 + tid];
        int ch  = idx / 9;
        int pos = idx - ch * 9;
        int ki  = pos / 3;
        int kj  = pos - ki * 3;
        // leaves 0..3 come from channel A, 4..7 from channel B (by construction)
        s_off[tid] = (tid >> 2) * PLANE + ki * PW + kj;
        if ((tid & 3) == 0) s_chan[tid >> 2] = ch;
    }
    if (tid < 16) s_coef[tid] = g_coef[oc * 16 + tid];
    __syncthreads();

    // Stage 2 zero-padded planes
    const float* xb = x + (size_t)b * C_IN * HH * WW;
    const int chA = s_chan[0], chB = s_chan[1];
    for (int i = tid; i < 2 * PLANE; i += 256) {
        int p  = i >= PLANE;
        int j  = i - p * PLANE;
        int r  = j / PW;
        int c  = j - r * PW;
        int gy = r - 1, gx = c - 1;
        float v = 0.f;
        if ((unsigned)gy < HH && (unsigned)gx < WW)
            v = xb[(p ? chB : chA) * (HH * WW) + gy * WW + gx];
        sm[i] = v;
    }
    __syncthreads();

    // Coefficients to registers
    float k0[4], k1[4], k2[4], k3[4];
    #pragma unroll
    for (int i = 0; i < 4; i++) { k0[i] = s_coef[i];      k1[i] = s_coef[4+i];
                                  k2[i] = s_coef[8+i];    k3[i] = s_coef[12+i]; }
    const int o0 = s_off[0], o1 = s_off[1], o2 = s_off[2], o3 = s_off[3];
    const int o4 = s_off[4], o5 = s_off[5], o6 = s_off[6], o7 = s_off[7];

    float* ob = out + (size_t)blk * (HH * WW);

    #pragma unroll
    for (int t = 0; t < 4; t++) {
        int pix = tid + t * 256;
        int y   = pix >> 5;
        int xx  = pix & 31;
        int pb  = y * PW + xx;

        float l0 = sm[o0 + pb], l1 = sm[o1 + pb];
        float l2 = sm[o2 + pb], l3 = sm[o3 + pb];
        float l4 = sm[o4 + pb], l5 = sm[o5 + pb];
        float l6 = sm[o6 + pb], l7 = sm[o7 + pb];

        // level 0: gates use weight rows 0,1,2,3
        float m0 = gate(k0[0], k0[1], k0[2], k0[3], l0, l1);
        float m1 = gate(k1[0], k1[1], k1[2], k1[3], l2, l3);
        float m2 = gate(k2[0], k2[1], k2[2], k2[3], l4, l5);
        float m3 = gate(k3[0], k3[1], k3[2], k3[3], l6, l7);
        // level 1: gate_ids = 2^1-1 + [0,1] = rows 1,2
        float n0 = gate(k1[0], k1[1], k1[2], k1[3], m0, m1);
        float n1 = gate(k2[0], k2[1], k2[2], k2[3], m2, m3);
        // level 2: gate_id = 2^2-1 = row 3
        float r  = gate(k3[0], k3[1], k3[2], k3[3], n0, n1);

        ob[pix] = r;
    }
}

extern "C" void kernel_launch(void* const* d_in, const int* in_sizes, int n_in,
                              void* d_out, int out_size)
{
    const float* x   = (const float*)d_in[0];          // [16,64,32,32]
    const float* w   = (const float*)d_in[1];          // [128,7,16]
    const int*   idx = (const int*)d_in[2];            // [128,8]
    float*       out = (float*)d_out;                  // [16,128,32,32]

    coef_kernel<<<2, 256>>>(w);
    tree_kernel<<<BATCH * C_OUT, 256>>>(x, idx, out);
}

// round 2
// speedup vs baseline: 1.3928x; 1.3928x over previous
#include <cuda_runtime.h>
#include <cstdint>

// Problem constants (fixed by the dataset)
#define BATCH   16
#define C_IN    64
#define HH      32
#define WW      32
#define C_OUT   128
#define NGATE   4          // only weight rows 0..3 are ever used by the tree
#define PH      34         // padded plane height
#define PW      34         // padded plane width
#define PLANE   (PH*PW)    // 1156

// Scratch: per-(oc,gate) affine coefficients {c0, ca, cb, cab}
__device__ float g_coef[C_OUT * NGATE * 4];

// ---------------------------------------------------------------------------
// Kernel 1: softmax over the 16 ops, collapsed to 4 affine coefficients.
// Each of the 16 binary ops equals c0 + ca*a + cb*b + cab*a*b.
// ---------------------------------------------------------------------------
__global__ void coef_kernel(const float* __restrict__ w)
{
    // op order: 0, ab, a-ab, a, b-ab, b, s-2ab, s-ab, 1-(s-ab), 1-(s-2ab),
    //           1-b, 1-b+ab, 1-a, 1-a+ab, 1-ab, 1
    const float T0[16]  = {0,0,0,0,0,0,0,0, 1, 1, 1, 1, 1, 1, 1, 1};
    const float TA[16]  = {0,0,1,1,0,0,1,1,-1,-1, 0, 0,-1,-1, 0, 0};
    const float TB[16]  = {0,0,0,0,1,1,1,1,-1,-1,-1,-1, 0, 0, 0, 0};
    const float TAB[16] = {0,1,-1,0,-1,0,-2,-1, 1, 2, 0, 1, 0, 1,-1, 0};

    int t = blockIdx.x * blockDim.x + threadIdx.x;
    if (t >= C_OUT * NGATE) return;
    int oc = t >> 2;
    int g  = t & 3;
    const float* wp = w + (oc * 7 + g) * 16;   // weights are [C_out, 7, 16]

    float m = wp[0];
    #pragma unroll
    for (int i = 1; i < 16; i++) m = fmaxf(m, wp[i]);

    float e[16];
    float s = 0.f;
    #pragma unroll
    for (int i = 0; i < 16; i++) { e[i] = __expf(wp[i] - m); s += e[i]; }
    float inv = 1.f / s;

    float c0 = 0.f, ca = 0.f, cb = 0.f, cab = 0.f;
    #pragma unroll
    for (int i = 0; i < 16; i++) {
        c0  += e[i] * T0[i];
        ca  += e[i] * TA[i];
        cb  += e[i] * TB[i];
        cab += e[i] * TAB[i];
    }
    float* o = g_coef + t * 4;
    o[0] = c0 * inv; o[1] = ca * inv; o[2] = cb * inv; o[3] = cab * inv;
}

// gate(a,b) = c0 + ca*a + cb*b + cab*a*b
__device__ __forceinline__ float gate(float c0, float ca, float cb, float cab,
                                      float a, float b)
{
    return fmaf(cab, a * b, fmaf(cb, b, fmaf(ca, a, c0)));
}

// ---------------------------------------------------------------------------
// Kernel 2: one block per (batch, out_channel).
// Stage the 2 source channel planes (zero-padded 34x34) in smem via float4
// zero-fill + float4 interior copy (no divisions, no predicates), then each
// thread evaluates 4 pixels; all smem/global addresses in the hot loop use
// compile-time immediate offsets.
// ---------------------------------------------------------------------------
__global__ void __launch_bounds__(256)
tree_kernel(const float* __restrict__ x,
            const int*   __restrict__ leaf_idx,
            float*       __restrict__ out)
{
    __shared__ __align__(16) float sm[2 * PLANE];   // two padded planes
    __shared__ int   s_off[8];        // per-leaf: plane_base + ki*PW + kj
    __shared__ int   s_chan[2];       // the two source channels
    __shared__ float s_coef[16];      // 4 gates x {c0,ca,cb,cab}

    const int blk = blockIdx.x;       // = b*C_OUT + oc
    const int oc  = blk & (C_OUT - 1);
    const int b   = blk >> 7;
    const int tid = threadIdx.x;

    if (tid < 8) {
        int idx = leaf_idx[oc * 8 + tid];
        int ch  = idx / 9;
        int pos = idx - ch * 9;
        int ki  = pos / 3;
        int kj  = pos - ki * 3;
        // leaves 0..3 come from channel A, 4..7 from channel B (by construction)
        s_off[tid] = (tid >> 2) * PLANE + ki * PW + kj;
        if ((tid & 3) == 0) s_chan[tid >> 2] = ch;
    }
    if (tid < 16) s_coef[tid] = g_coef[oc * 16 + tid];

    // --- zero-fill both padded planes (covers the borders) ---------------
    // 2*PLANE = 2312 floats = 578 float4
    {
        float4 z = make_float4(0.f, 0.f, 0.f, 0.f);
        float4* smv = (float4*)sm;
        #pragma unroll
        for (int i = 0; i < 3; i++) {
            int j = tid + i * 256;
            if (j < 578) smv[j] = z;
        }
    }
    __syncthreads();

    // --- interior copy: 2 planes x 32 rows x 8 float4 = 512 vec loads ----
    {
        const float* xb = x + ((size_t)b * C_IN) * (HH * WW);
        const float4* srcA = (const float4*)(xb + s_chan[0] * (HH * WW));
        const float4* srcB = (const float4*)(xb + s_chan[1] * (HH * WW));
        #pragma unroll
        for (int i = 0; i < 2; i++) {
            int t   = tid + i * 256;      // 0..511
            int p   = t >> 8;             // plane select
            int j   = t & 255;            // 0..255 : r*8 + c4
            int r   = j >> 3;
            int c4  = j & 7;
            float4 v = p ? srcB[j] : srcA[j];
            float* dst = sm + p * PLANE + (r + 1) * PW + 1 + c4 * 4;
            dst[0] = v.x; dst[1] = v.y; dst[2] = v.z; dst[3] = v.w;
        }
    }
    __syncthreads();

    // Coefficients to registers
    float k0[4], k1[4], k2[4], k3[4];
    #pragma unroll
    for (int i = 0; i < 4; i++) { k0[i] = s_coef[i];      k1[i] = s_coef[4+i];
                                  k2[i] = s_coef[8+i];    k3[i] = s_coef[12+i]; }

    // Per-thread base pixel: pix0 = tid, y0 = tid>>5, x0 = tid&31
    const int pb0 = (tid >> 5) * PW + (tid & 31);

    // 8 leaf base pointers (hoisted); hot loop indexes with immediates
    const float* p0 = sm + s_off[0] + pb0;
    const float* p1 = sm + s_off[1] + pb0;
    const float* p2 = sm + s_off[2] + pb0;
    const float* p3 = sm + s_off[3] + pb0;
    const float* p4 = sm + s_off[4] + pb0;
    const float* p5 = sm + s_off[5] + pb0;
    const float* p6 = sm + s_off[6] + pb0;
    const float* p7 = sm + s_off[7] + pb0;

    float* ob = out + (size_t)blk * (HH * WW) + tid;

    #pragma unroll
    for (int t = 0; t < 4; t++) {
        const int d = t * 8 * PW;        // +8 rows per step (256 pixels)

        float l0 = p0[d], l1 = p1[d];
        float l2 = p2[d], l3 = p3[d];
        float l4 = p4[d], l5 = p5[d];
        float l6 = p6[d], l7 = p7[d];

        // level 0: gates use weight rows 0,1,2,3
        float m0 = gate(k0[0], k0[1], k0[2], k0[3], l0, l1);
        float m1 = gate(k1[0], k1[1], k1[2], k1[3], l2, l3);
        float m2 = gate(k2[0], k2[1], k2[2], k2[3], l4, l5);
        float m3 = gate(k3[0], k3[1], k3[2], k3[3], l6, l7);
        // level 1: gate_ids = 2^1-1 + [0,1] = rows 1,2
        float n0 = gate(k1[0], k1[1], k1[2], k1[3], m0, m1);
        float n1 = gate(k2[0], k2[1], k2[2], k2[3], m2, m3);
        // level 2: gate_id = 2^2-1 = row 3
        float r  = gate(k3[0], k3[1], k3[2], k3[3], n0, n1);

        ob[t * 256] = r;
    }
}

extern "C" void kernel_launch(void* const* d_in, const int* in_sizes, int n_in,
                              void* d_out, int out_size)
{
    const float* x   = (const float*)d_in[0];          // [16,64,32,32]
    const float* w   = (const float*)d_in[1];          // [128,7,16]
    const int*   idx = (const int*)d_in[2];            // [128,8]
    float*       out = (float*)d_out;                  // [16,128,32,32]

    coef_kernel<<<2, 256>>>(w);
    tree_kernel<<<BATCH * C_OUT, 256>>>(x, idx, out);
}

// round 3
// speedup vs baseline: 1.9524x; 1.4018x over previous
#include <cuda_runtime.h>
#include <cstdint>

// Problem constants (fixed by the dataset)
#define BATCH   16
#define C_IN    64
#define HH      32
#define WW      32
#define C_OUT   128
#define PH      34         // padded plane height
#define PW      34         // padded plane width
#define PLANE   (PH*PW)    // 1156

// gate(a,b) = c0 + ca*a + cb*b + cab*a*b
__device__ __forceinline__ float gate(float c0, float ca, float cb, float cab,
                                      float a, float b)
{
    return fmaf(cab, a * b, fmaf(cb, b, fmaf(ca, a, c0)));
}

// ---------------------------------------------------------------------------
// Single fused kernel: one block per (batch, out_channel).
//  - threads 0..3 compute the softmax-collapsed affine coefficients for the
//    4 weight rows this oc's tree uses (rows 0..3), overlapped with staging
//  - all threads stage the 2 source channel planes (zero-padded 34x34) in
//    smem via float4 zero-fill + float4 interior copy
//  - each thread evaluates 4 pixels through the 7-gate soft logic tree with
//    compile-time immediate addressing in the hot loop
// ---------------------------------------------------------------------------
__global__ void __launch_bounds__(256)
tree_kernel(const float* __restrict__ x,
            const float* __restrict__ w,
            const int*   __restrict__ leaf_idx,
            float*       __restrict__ out)
{
    __shared__ __align__(16) float sm[2 * PLANE];   // two padded planes
    __shared__ int   s_off[8];        // per-leaf: plane_base + ki*PW + kj
    __shared__ int   s_chan[2];       // the two source channels
    __shared__ float s_coef[16];      // 4 gates x {c0,ca,cb,cab}

    const int blk = blockIdx.x;       // = b*C_OUT + oc
    const int oc  = blk & (C_OUT - 1);
    const int b   = blk >> 7;
    const int tid = threadIdx.x;

    // --- zero-fill both padded planes (covers the borders) ---------------
    // 2*PLANE = 2312 floats = 578 float4
    {
        float4 z = make_float4(0.f, 0.f, 0.f, 0.f);
        float4* smv = (float4*)sm;
        #pragma unroll
        for (int i = 0; i < 3; i++) {
            int j = tid + i * 256;
            if (j < 578) smv[j] = z;
        }
    }

    if (tid < 8) {
        int idx = leaf_idx[oc * 8 + tid];
        int ch  = idx / 9;
        int pos = idx - ch * 9;
        int ki  = pos / 3;
        int kj  = pos - ki * 3;
        // leaves 0..3 come from channel A, 4..7 from channel B (by construction)
        s_off[tid] = (tid >> 2) * PLANE + ki * PW + kj;
        if ((tid & 3) == 0) s_chan[tid >> 2] = ch;
    }

    // --- softmax -> 4 affine coefficients, threads 0..3 (gate = tid) -----
    // Each of the 16 binary ops equals c0 + ca*a + cb*b + cab*a*b.
    // op order: 0, ab, a-ab, a, b-ab, b, s-2ab, s-ab, 1-(s-ab), 1-(s-2ab),
    //           1-b, 1-b+ab, 1-a, 1-a+ab, 1-ab, 1
    if (tid < 4) {
        const float T0[16]  = {0,0,0,0,0,0,0,0, 1, 1, 1, 1, 1, 1, 1, 1};
        const float TA[16]  = {0,0,1,1,0,0,1,1,-1,-1, 0, 0,-1,-1, 0, 0};
        const float TB[16]  = {0,0,0,0,1,1,1,1,-1,-1,-1,-1, 0, 0, 0, 0};
        const float TAB[16] = {0,1,-1,0,-1,0,-2,-1, 1, 2, 0, 1, 0, 1,-1, 0};

        const float* wp = w + (oc * 7 + tid) * 16;   // weights are [C_out, 7, 16]

        float m = wp[0];
        #pragma unroll
        for (int i = 1; i < 16; i++) m = fmaxf(m, wp[i]);

        float e[16];
        float s = 0.f;
        #pragma unroll
        for (int i = 0; i < 16; i++) { e[i] = __expf(wp[i] - m); s += e[i]; }
        float inv = 1.f / s;

        float c0 = 0.f, ca = 0.f, cb = 0.f, cab = 0.f;
        #pragma unroll
        for (int i = 0; i < 16; i++) {
            c0  += e[i] * T0[i];
            ca  += e[i] * TA[i];
            cb  += e[i] * TB[i];
            cab += e[i] * TAB[i];
        }
        s_coef[tid * 4 + 0] = c0 * inv;
        s_coef[tid * 4 + 1] = ca * inv;
        s_coef[tid * 4 + 2] = cb * inv;
        s_coef[tid * 4 + 3] = cab * inv;
    }
    __syncthreads();

    // --- interior copy: 2 planes x 32 rows x 8 float4 = 512 vec loads ----
    {
        const float* xb = x + ((size_t)b * C_IN) * (HH * WW);
        const float4* srcA = (const float4*)(xb + s_chan[0] * (HH * WW));
        const float4* srcB = (const float4*)(xb + s_chan[1] * (HH * WW));
        #pragma unroll
        for (int i = 0; i < 2; i++) {
            int t   = tid + i * 256;      // 0..511
            int p   = t >> 8;             // plane select
            int j   = t & 255;            // 0..255 : r*8 + c4
            int r   = j >> 3;
            int c4  = j & 7;
            float4 v = p ? srcB[j] : srcA[j];
            float* dst = sm + p * PLANE + (r + 1) * PW + 1 + c4 * 4;
            dst[0] = v.x; dst[1] = v.y; dst[2] = v.z; dst[3] = v.w;
        }
    }
    __syncthreads();

    // Coefficients to registers
    float k0[4], k1[4], k2[4], k3[4];
    #pragma unroll
    for (int i = 0; i < 4; i++) { k0[i] = s_coef[i];      k1[i] = s_coef[4+i];
                                  k2[i] = s_coef[8+i];    k3[i] = s_coef[12+i]; }

    // Per-thread base pixel: pix0 = tid, y0 = tid>>5, x0 = tid&31
    const int pb0 = (tid >> 5) * PW + (tid & 31);

    // 8 leaf base pointers (hoisted); hot loop indexes with immediates
    const float* p0 = sm + s_off[0] + pb0;
    const float* p1 = sm + s_off[1] + pb0;
    const float* p2 = sm + s_off[2] + pb0;
    const float* p3 = sm + s_off[3] + pb0;
    const float* p4 = sm + s_off[4] + pb0;
    const float* p5 = sm + s_off[5] + pb0;
    const float* p6 = sm + s_off[6] + pb0;
    const float* p7 = sm + s_off[7] + pb0;

    float* ob = out + (size_t)blk * (HH * WW) + tid;

    #pragma unroll
    for (int t = 0; t < 4; t++) {
        const int d = t * 8 * PW;        // +8 rows per step (256 pixels)

        float l0 = p0[d], l1 = p1[d];
        float l2 = p2[d], l3 = p3[d];
        float l4 = p4[d], l5 = p5[d];
        float l6 = p6[d], l7 = p7[d];

        // level 0: gates use weight rows 0,1,2,3
        float m0 = gate(k0[0], k0[1], k0[2], k0[3], l0, l1);
        float m1 = gate(k1[0], k1[1], k1[2], k1[3], l2, l3);
        float m2 = gate(k2[0], k2[1], k2[2], k2[3], l4, l5);
        float m3 = gate(k3[0], k3[1], k3[2], k3[3], l6, l7);
        // level 1: gate_ids = 2^1-1 + [0,1] = rows 1,2
        float n0 = gate(k1[0], k1[1], k1[2], k1[3], m0, m1);
        float n1 = gate(k2[0], k2[1], k2[2], k2[3], m2, m3);
        // level 2: gate_id = 2^2-1 = row 3
        float r  = gate(k3[0], k3[1], k3[2], k3[3], n0, n1);

        ob[t * 256] = r;
    }
}

extern "C" void kernel_launch(void* const* d_in, const int* in_sizes, int n_in,
                              void* d_out, int out_size)
{
    const float* x   = (const float*)d_in[0];          // [16,64,32,32]
    const float* w   = (const float*)d_in[1];          // [128,7,16]
    const int*   idx = (const int*)d_in[2];            // [128,8]
    float*       out = (float*)d_out;                  // [16,128,32,32]

    tree_kernel<<<BATCH * C_OUT, 256>>>(x, w, idx, out);
}